// round 3
// baseline (speedup 1.0000x reference)
#include <cuda_runtime.h>

#define NRES 384
#define CH 128
#define NN (NRES*NRES)
#define EPSF 1e-5f

// ---- scratch (device globals; no allocation) ----
__device__ float g_at[CH*NN];     // a transposed [h][i*384+k]
__device__ float g_bt[CH*NN];     // b transposed [h][j*384+k]
__device__ float g_gate[NN*CH];   // sigmoid gate, row-major
__device__ float g_xt[CH*NN];     // triangle out [h][i*384+j]
__device__ float g_wT[6*CH*CH];   // transposed weights

__device__ __forceinline__ float sigf(float x){ return 1.f/(1.f+__expf(-x)); }

// ---- packed f32x2 helpers (Blackwell FFMA2 via PTX) ----
__device__ __forceinline__ unsigned long long dup2(float x){
    unsigned long long r; asm("mov.b64 %0, {%1, %1};" : "=l"(r) : "f"(x)); return r;
}
__device__ __forceinline__ void fma2(unsigned long long &d, unsigned long long a, unsigned long long b){
    asm("fma.rn.f32x2 %0, %1, %2, %0;" : "+l"(d) : "l"(a), "l"(b));
}
__device__ __forceinline__ float2 unpk(unsigned long long v){
    float2 r; asm("mov.b64 {%0, %1}, %2;" : "=f"(r.x), "=f"(r.y) : "l"(v)); return r;
}

// ---- 128x128 transpose into g_wT[idx] ----
__global__ void transpose128(const float* __restrict__ src, int idx){
    __shared__ float t[32][33];
    float* dst = g_wT + idx*CH*CH;
    int x0=blockIdx.x*32, y0=blockIdx.y*32;
    int tx=threadIdx.x, ty=threadIdx.y;
    #pragma unroll
    for (int j=0;j<32;j+=8) t[ty+j][tx] = src[(y0+ty+j)*CH + x0+tx];
    __syncthreads();
    #pragma unroll
    for (int j=0;j<32;j+=8) dst[(x0+ty+j)*CH + y0+tx] = t[tx][ty+j];
}

// ---- fused LN + 5 GEMMs + gated epilogues; 32 rows/block ----
__global__ __launch_bounds__(256)
void proj_kernel(const float* __restrict__ z, const float* __restrict__ mask,
                 const float* __restrict__ lnw, const float* __restrict__ lnb,
                 const float* __restrict__ agb, const float* __restrict__ apb,
                 const float* __restrict__ bgb, const float* __restrict__ bpb,
                 const float* __restrict__ gb)
{
    __shared__ float z_s[32*132];
    __shared__ float wg_s[8*132];
    __shared__ float wp_s[8*132];
    __shared__ float ot[128*34];
    int tid = threadIdx.x;
    int row0 = blockIdx.x*32;

    const float4* z4 = (const float4*)(z + (size_t)row0*CH);
    #pragma unroll
    for (int it=0; it<4; ++it){
        int f = tid + it*256;
        int r = f>>5, c4 = f&31;
        *(float4*)(z_s + r*132 + c4*4) = z4[f];
    }
    __syncthreads();

    int lane = tid&31, wid = tid>>5;
    #pragma unroll
    for (int rr=0; rr<4; ++rr){
        int r = wid*4+rr;
        float v[4], s=0.f, q=0.f;
        #pragma unroll
        for (int m=0;m<4;++m){ float x=z_s[r*132+lane+32*m]; v[m]=x; s+=x; q+=x*x; }
        #pragma unroll
        for (int o=16;o>0;o>>=1){ s+=__shfl_xor_sync(0xffffffffu,s,o); q+=__shfl_xor_sync(0xffffffffu,q,o); }
        float mu=s*(1.f/128.f), var=q*(1.f/128.f)-mu*mu;
        float rs=rsqrtf(fmaxf(var,0.f)+EPSF);
        #pragma unroll
        for (int m=0;m<4;++m){
            int c=lane+32*m;
            z_s[r*132+c] = (v[m]-mu)*rs*lnw[c]+lnb[c];
        }
    }
    __syncthreads();

    int tx = tid&15, ty = tid>>4;
    const float* WgT[3] = {g_wT, g_wT+2*CH*CH, g_wT+4*CH*CH};
    const float* WpT[3] = {g_wT+CH*CH, g_wT+3*CH*CH, 0};
    const float* GB[3]  = {agb, bgb, gb};
    const float* PB[3]  = {apb, bpb, 0};

    for (int ph=0; ph<3; ++ph){
        bool hasP = (ph<2);
        unsigned long long accg[2][4], accp[2][4];
        #pragma unroll
        for (int u=0;u<2;++u)
            #pragma unroll
            for (int v=0;v<4;++v){ accg[u][v]=0ull; accp[u][v]=0ull; }

        for (int c0=0;c0<CH;c0+=8){
            int c=tid>>5, o4=tid&31;
            *(float4*)(wg_s + c*132 + o4*4) = *(const float4*)(WgT[ph] + (c0+c)*CH + o4*4);
            if (hasP)
                *(float4*)(wp_s + c*132 + o4*4) = *(const float4*)(WpT[ph] + (c0+c)*CH + o4*4);
            __syncthreads();
            #pragma unroll
            for (int i=0;i<8;++i){
                unsigned long long z0 = dup2(z_s[(ty*2+0)*132 + c0+i]);
                unsigned long long z1 = dup2(z_s[(ty*2+1)*132 + c0+i]);
                ulonglong2 wa = *(const ulonglong2*)(wg_s + i*132 + tx*8);
                ulonglong2 wb = *(const ulonglong2*)(wg_s + i*132 + tx*8 + 4);
                fma2(accg[0][0],z0,wa.x); fma2(accg[0][1],z0,wa.y);
                fma2(accg[0][2],z0,wb.x); fma2(accg[0][3],z0,wb.y);
                fma2(accg[1][0],z1,wa.x); fma2(accg[1][1],z1,wa.y);
                fma2(accg[1][2],z1,wb.x); fma2(accg[1][3],z1,wb.y);
                if (hasP){
                    ulonglong2 pa = *(const ulonglong2*)(wp_s + i*132 + tx*8);
                    ulonglong2 pb4= *(const ulonglong2*)(wp_s + i*132 + tx*8 + 4);
                    fma2(accp[0][0],z0,pa.x); fma2(accp[0][1],z0,pa.y);
                    fma2(accp[0][2],z0,pb4.x);fma2(accp[0][3],z0,pb4.y);
                    fma2(accp[1][0],z1,pa.x); fma2(accp[1][1],z1,pa.y);
                    fma2(accp[1][2],z1,pb4.x);fma2(accp[1][3],z1,pb4.y);
                }
            }
            __syncthreads();
        }

        if (hasP){
            float* dstT = ph ? g_bt : g_at;
            #pragma unroll
            for (int u=0;u<2;++u){
                int r = ty*2+u;
                float mk = mask[row0+r];
                #pragma unroll
                for (int v=0;v<4;++v){
                    float2 gv = unpk(accg[u][v]);
                    float2 pv = unpk(accp[u][v]);
                    int o = tx*8+v*2;
                    ot[(o+0)*34 + r] = mk * sigf(gv.x+GB[ph][o+0]) * (pv.x+PB[ph][o+0]);
                    ot[(o+1)*34 + r] = mk * sigf(gv.y+GB[ph][o+1]) * (pv.y+PB[ph][o+1]);
                }
            }
            __syncthreads();
            #pragma unroll
            for (int it=0; it<16; ++it){
                int f = tid + it*256;
                int r=f&31, o=f>>5;
                dstT[(size_t)o*NN + row0 + r] = ot[o*34+r];
            }
            __syncthreads();
        } else {
            #pragma unroll
            for (int u=0;u<2;++u){
                int grow = row0 + ty*2+u;
                #pragma unroll
                for (int v=0;v<4;++v){
                    float2 gv = unpk(accg[u][v]);
                    int o=tx*8+v*2;
                    g_gate[(size_t)grow*CH + o+0] = sigf(gv.x+gb[o+0]);
                    g_gate[(size_t)grow*CH + o+1] = sigf(gv.y+gb[o+1]);
                }
            }
        }
    }
}

// ---- per-channel triangle GEMM: X_h = A_h @ B_h^T ----
__global__ __launch_bounds__(256)
void tri_kernel(){
    __shared__ float At[16*132], Bt[16*132];
    int h = blockIdx.z;
    int i0 = blockIdx.y*128, j0 = blockIdx.x*128;
    const float* A = g_at + (size_t)h*NN;
    const float* B = g_bt + (size_t)h*NN;
    int tid=threadIdx.x, tx=tid&15, ty=tid>>4;
    unsigned long long acc[8][4];
    #pragma unroll
    for (int r=0;r<8;++r)
        #pragma unroll
        for (int c=0;c<4;++c) acc[r][c]=0ull;

    for (int k0=0;k0<NRES;k0+=16){
        #pragma unroll
        for (int it=0; it<2; ++it){
            int f = tid + it*256;
            int i = f>>2, k4 = (f&3)*4;
            float4 va = *(const float4*)(A + (size_t)(i0+i)*NRES + k0 + k4);
            At[(k4+0)*132+i]=va.x; At[(k4+1)*132+i]=va.y; At[(k4+2)*132+i]=va.z; At[(k4+3)*132+i]=va.w;
            float4 vb = *(const float4*)(B + (size_t)(j0+i)*NRES + k0 + k4);
            Bt[(k4+0)*132+i]=vb.x; Bt[(k4+1)*132+i]=vb.y; Bt[(k4+2)*132+i]=vb.z; Bt[(k4+3)*132+i]=vb.w;
        }
        __syncthreads();
        #pragma unroll
        for (int kk=0;kk<16;++kk){
            float a[8];
            *(float4*)(a)   = *(float4*)(At + kk*132 + ty*8);
            *(float4*)(a+4) = *(float4*)(At + kk*132 + ty*8 + 4);
            ulonglong2 b0 = *(const ulonglong2*)(Bt + kk*132 + tx*8);
            ulonglong2 b1 = *(const ulonglong2*)(Bt + kk*132 + tx*8 + 4);
            #pragma unroll
            for (int r=0;r<8;++r){
                unsigned long long ar = dup2(a[r]);
                fma2(acc[r][0], ar, b0.x);
                fma2(acc[r][1], ar, b0.y);
                fma2(acc[r][2], ar, b1.x);
                fma2(acc[r][3], ar, b1.y);
            }
        }
        __syncthreads();
    }
    float* X = g_xt + (size_t)h*NN + (size_t)i0*NRES + j0;
    #pragma unroll
    for (int r=0;r<8;++r){
        float2 c0=unpk(acc[r][0]), c1=unpk(acc[r][1]), c2=unpk(acc[r][2]), c3=unpk(acc[r][3]);
        float4* p = (float4*)(X + (size_t)(ty*8+r)*NRES + tx*8);
        p[0] = make_float4(c0.x,c0.y,c1.x,c1.y);
        p[1] = make_float4(c2.x,c2.y,c3.x,c3.y);
    }
}

// ---- LN over h + output GEMM + gate; 64 rows/block ----
__global__ __launch_bounds__(256)
void out_kernel(const float* __restrict__ low, const float* __restrict__ lob,
                const float* __restrict__ zb, float* __restrict__ out)
{
    __shared__ float xs[128*66];
    __shared__ float zw_s[16*132];
    __shared__ float mu_s[64], rs_s[64];
    __shared__ float low_s[128], lob_s[128];
    int tid=threadIdx.x;
    int row0 = blockIdx.x*64;
    if (tid<128){ low_s[tid]=low[tid]; lob_s[tid]=lob[tid]; }
    #pragma unroll
    for (int it=0; it<32; ++it){
        int f = tid + it*256;
        int r = f&63, h = f>>6;
        xs[h*66 + r] = g_xt[(size_t)h*NN + row0 + r];
    }
    __syncthreads();
    int lane=tid&31, wid=tid>>5;
    #pragma unroll
    for (int rr=0;rr<8;++rr){
        int r = wid*8+rr;
        float s=0.f,q=0.f;
        #pragma unroll
        for (int m=0;m<4;++m){ float x=xs[(lane+32*m)*66 + r]; s+=x; q+=x*x; }
        #pragma unroll
        for (int o=16;o>0;o>>=1){ s+=__shfl_xor_sync(0xffffffffu,s,o); q+=__shfl_xor_sync(0xffffffffu,q,o); }
        if (lane==0){
            float mu=s*(1.f/128.f), var=q*(1.f/128.f)-mu*mu;
            mu_s[r]=mu; rs_s[r]=rsqrtf(fmaxf(var,0.f)+EPSF);
        }
    }
    __syncthreads();
    int tx=tid&15, ty=tid>>4;
    unsigned long long acc[4][4];
    #pragma unroll
    for (int u=0;u<4;++u)
        #pragma unroll
        for (int v=0;v<4;++v) acc[u][v]=0ull;
    float mu[4], rs[4];
    #pragma unroll
    for (int u=0;u<4;++u){ mu[u]=mu_s[ty*4+u]; rs[u]=rs_s[ty*4+u]; }
    const float* zwT = g_wT + 5*CH*CH;

    for (int h0=0;h0<CH;h0+=16){
        #pragma unroll
        for (int it=0; it<2; ++it){
            int f=tid+it*256;
            int hh=f>>5, o4=f&31;
            *(float4*)(zw_s + hh*132 + o4*4) = *(const float4*)(zwT + (h0+hh)*CH + o4*4);
        }
        __syncthreads();
        #pragma unroll
        for (int hh=0; hh<16; ++hh){
            int h=h0+hh;
            float lw=low_s[h], lb=lob_s[h];
            ulonglong2 w0 = *(const ulonglong2*)(zw_s + hh*132 + tx*8);
            ulonglong2 w1 = *(const ulonglong2*)(zw_s + hh*132 + tx*8 + 4);
            #pragma unroll
            for (int u=0;u<4;++u){
                unsigned long long xn = dup2((xs[h*66 + ty*4+u]-mu[u])*rs[u]*lw + lb);
                fma2(acc[u][0], xn, w0.x);
                fma2(acc[u][1], xn, w0.y);
                fma2(acc[u][2], xn, w1.x);
                fma2(acc[u][3], xn, w1.y);
            }
        }
        __syncthreads();
    }
    #pragma unroll
    for (int u=0;u<4;++u){
        int grow=row0+ty*4+u;
        const float4* g4 = (const float4*)(g_gate + (size_t)grow*CH + tx*8);
        const float4* b4 = (const float4*)(zb + tx*8);
        float4* o4p = (float4*)(out + (size_t)grow*CH + tx*8);
        float2 c0=unpk(acc[u][0]), c1=unpk(acc[u][1]), c2=unpk(acc[u][2]), c3=unpk(acc[u][3]);
        float av[8] = {c0.x,c0.y,c1.x,c1.y,c2.x,c2.y,c3.x,c3.y};
        #pragma unroll
        for (int w2=0;w2<2;++w2){
            float4 g=g4[w2], b=b4[w2];
            o4p[w2] = make_float4(g.x*(av[w2*4+0]+b.x),
                                  g.y*(av[w2*4+1]+b.y),
                                  g.z*(av[w2*4+2]+b.z),
                                  g.w*(av[w2*4+3]+b.w));
        }
    }
}

extern "C" void kernel_launch(void* const* d_in, const int* in_sizes, int n_in,
                              void* d_out, int out_size) {
    const float* z      = (const float*)d_in[0];
    const float* mask   = (const float*)d_in[1];
    const float* ln_in_w= (const float*)d_in[2];
    const float* ln_in_b= (const float*)d_in[3];
    const float* a_g_w  = (const float*)d_in[4];
    const float* a_g_b  = (const float*)d_in[5];
    const float* a_p_w  = (const float*)d_in[6];
    const float* a_p_b  = (const float*)d_in[7];
    const float* b_g_w  = (const float*)d_in[8];
    const float* b_g_b  = (const float*)d_in[9];
    const float* b_p_w  = (const float*)d_in[10];
    const float* b_p_b  = (const float*)d_in[11];
    const float* g_w    = (const float*)d_in[12];
    const float* g_b    = (const float*)d_in[13];
    const float* ln_out_w=(const float*)d_in[14];
    const float* ln_out_b=(const float*)d_in[15];
    const float* z_w    = (const float*)d_in[16];
    const float* z_b    = (const float*)d_in[17];
    float* out = (float*)d_out;

    dim3 tb(32,8), tg(4,4);
    transpose128<<<tg,tb>>>(a_g_w,0);
    transpose128<<<tg,tb>>>(a_p_w,1);
    transpose128<<<tg,tb>>>(b_g_w,2);
    transpose128<<<tg,tb>>>(b_p_w,3);
    transpose128<<<tg,tb>>>(g_w,4);
    transpose128<<<tg,tb>>>(z_w,5);

    proj_kernel<<<NN/32,256>>>(z, mask, ln_in_w, ln_in_b,
                               a_g_b, a_p_b, b_g_b, b_p_b, g_b);
    tri_kernel<<<dim3(3,3,128),256>>>();
    out_kernel<<<NN/64,256>>>(ln_out_w, ln_out_b, z_b, out);
}